// round 2
// baseline (speedup 1.0000x reference)
#include <cuda_runtime.h>
#include <cuda_bf16.h>
#include <cstdint>

#define M_DIM 8192
#define N_DIM 4096
#define K_DIM 4096

// ---------------- scratch (device globals; no allocations allowed) ----------
// A packed as [K/32][M/16] tiles of 512B, each 16x32 u8 tile in IMMA a-frag order.
// B packed as [K/32][N/8]  tiles of 256B, each 32x8  s8 tile in IMMA b-frag order.
__device__ unsigned char g_Aq[(size_t)M_DIM * K_DIM];
__device__ unsigned char g_Bq[(size_t)N_DIM * K_DIM];
__device__ float g_sa[M_DIM];   // activation scale per token
__device__ int   g_zp[M_DIM];   // activation zero point per token
__device__ float g_sw[N_DIM];   // weight scale per row
__device__ int   g_sumw[N_DIM]; // sum_k Wq[n,k]

// ---------------- helpers ----------------------------------------------------
__device__ __forceinline__ uint32_t smem_u32(const void* p) {
    uint32_t a;
    asm("{ .reg .u64 t; cvta.to.shared.u64 t, %1; cvt.u32.u64 %0, t; }"
        : "=r"(a) : "l"(p));
    return a;
}

#define CP_ASYNC16(dst, src) \
    asm volatile("cp.async.cg.shared.global [%0], [%1], 16;" \
                 :: "r"(dst), "l"(src) : "memory")
#define CP_COMMIT() asm volatile("cp.async.commit_group;" ::: "memory")
#define CP_WAIT2()  asm volatile("cp.async.wait_group 2;" ::: "memory")

__device__ __forceinline__ void mma_u8s8(int* d, const unsigned* a, const unsigned* b) {
    asm volatile(
        "mma.sync.aligned.m16n8k32.row.col.s32.u8.s8.s32 "
        "{%0,%1,%2,%3}, {%4,%5,%6,%7}, {%8,%9}, {%0,%1,%2,%3};"
        : "+r"(d[0]), "+r"(d[1]), "+r"(d[2]), "+r"(d[3])
        : "r"(a[0]), "r"(a[1]), "r"(a[2]), "r"(a[3]),
          "r"(b[0]), "r"(b[1]));
}

// ---------------- quantization + fragment packing ----------------------------
// A tile (16x32 u8, 512B): lane t regs a0..a3 at byte t*16 + j*4 + (c&3)
//   j = (c>=16)*2 + (r>=8),  t = (r&7)*4 + ((c&15)>>2)
__global__ __launch_bounds__(256) void quant_x_kernel(const float* __restrict__ x) {
    int m = blockIdx.x;
    int tid = threadIdx.x;
    const float4* xr = (const float4*)(x + (size_t)m * K_DIM);
    float4 v[4];
    float mn = 3.4e38f, mx = -3.4e38f;
#pragma unroll
    for (int i = 0; i < 4; i++) {
        v[i] = xr[tid + i * 256];
        mn = fminf(mn, fminf(fminf(v[i].x, v[i].y), fminf(v[i].z, v[i].w)));
        mx = fmaxf(mx, fmaxf(fmaxf(v[i].x, v[i].y), fmaxf(v[i].z, v[i].w)));
    }
#pragma unroll
    for (int o = 16; o; o >>= 1) {
        mn = fminf(mn, __shfl_xor_sync(0xFFFFFFFFu, mn, o));
        mx = fmaxf(mx, __shfl_xor_sync(0xFFFFFFFFu, mx, o));
    }
    __shared__ float smn[8], smx[8];
    if ((tid & 31) == 0) { smn[tid >> 5] = mn; smx[tid >> 5] = mx; }
    __syncthreads();
    mn = smn[0]; mx = smx[0];
#pragma unroll
    for (int i = 1; i < 8; i++) { mn = fminf(mn, smn[i]); mx = fmaxf(mx, smx[i]); }

    float rng = mx - mn;
    float scale = (rng > 0.0f) ? rng * (1.0f / 255.0f) : 1.0f;
    float zpf = rintf(-mn / scale);
    if (tid == 0) { g_sa[m] = scale; g_zp[m] = (int)zpf; }

    int mt = m >> 4;
    int r = m & 15;
    uint32_t rbase = (uint32_t)(r & 7) * 64 + ((r >= 8) ? 4u : 0u);
    float inv = 1.0f / scale;
#pragma unroll
    for (int i = 0; i < 4; i++) {
        int f = tid + i * 256;
        int c4 = f * 4;            // k position of first of 4 consecutive elems
        int kt = c4 >> 5;
        int c = c4 & 31;
        float q0 = fminf(fmaxf(rintf(v[i].x * inv) + zpf, 0.0f), 255.0f);
        float q1 = fminf(fmaxf(rintf(v[i].y * inv) + zpf, 0.0f), 255.0f);
        float q2 = fminf(fmaxf(rintf(v[i].z * inv) + zpf, 0.0f), 255.0f);
        float q3 = fminf(fmaxf(rintf(v[i].w * inv) + zpf, 0.0f), 255.0f);
        uint32_t off_in = rbase + (uint32_t)((c & 15) >> 2) * 16 + ((c >= 16) ? 8u : 0u);
        size_t tile = ((size_t)kt * (M_DIM / 16) + mt) * 512;
        *(uchar4*)(g_Aq + tile + off_in) =
            make_uchar4((unsigned char)q0, (unsigned char)q1,
                        (unsigned char)q2, (unsigned char)q3);
    }
}

// B tile (32x8 s8, 256B): lane t regs b0,b1 at byte t*8 + (k>=16)*4 + (k&3)
//   t = c*4 + ((k&15)>>2), c = n&7
__global__ __launch_bounds__(256) void quant_w_kernel(const float* __restrict__ w) {
    int n = blockIdx.x;
    int tid = threadIdx.x;
    const float4* wr = (const float4*)(w + (size_t)n * K_DIM);
    float4 v[4];
    float am = 0.0f;
#pragma unroll
    for (int i = 0; i < 4; i++) {
        v[i] = wr[tid + i * 256];
        am = fmaxf(am, fmaxf(fmaxf(fabsf(v[i].x), fabsf(v[i].y)),
                             fmaxf(fabsf(v[i].z), fabsf(v[i].w))));
    }
#pragma unroll
    for (int o = 16; o; o >>= 1)
        am = fmaxf(am, __shfl_xor_sync(0xFFFFFFFFu, am, o));
    __shared__ float sam[8];
    __shared__ int ssum[8];
    if ((tid & 31) == 0) sam[tid >> 5] = am;
    __syncthreads();
    am = sam[0];
#pragma unroll
    for (int i = 1; i < 8; i++) am = fmaxf(am, sam[i]);

    float scale = (am > 0.0f) ? am * (1.0f / 127.0f) : 1.0f;
    float inv = 1.0f / scale;

    int nt = n >> 3;
    int c = n & 7;
    int mysum = 0;
#pragma unroll
    for (int i = 0; i < 4; i++) {
        int f = tid + i * 256;
        int c4 = f * 4;
        int kt = c4 >> 5;
        int kk = c4 & 31;
        float q0 = fminf(fmaxf(rintf(v[i].x * inv), -127.0f), 127.0f);
        float q1 = fminf(fmaxf(rintf(v[i].y * inv), -127.0f), 127.0f);
        float q2 = fminf(fmaxf(rintf(v[i].z * inv), -127.0f), 127.0f);
        float q3 = fminf(fmaxf(rintf(v[i].w * inv), -127.0f), 127.0f);
        int i0 = (int)q0, i1 = (int)q1, i2 = (int)q2, i3 = (int)q3;
        mysum += i0 + i1 + i2 + i3;
        uint32_t off_in = (uint32_t)c * 32 + (uint32_t)((kk & 15) >> 2) * 8 +
                          ((kk >= 16) ? 4u : 0u);
        size_t tile = ((size_t)kt * (N_DIM / 8) + nt) * 256;
        *(char4*)(g_Bq + tile + off_in) =
            make_char4((signed char)i0, (signed char)i1,
                       (signed char)i2, (signed char)i3);
    }
#pragma unroll
    for (int o = 16; o; o >>= 1)
        mysum += __shfl_xor_sync(0xFFFFFFFFu, mysum, o);
    if ((tid & 31) == 0) ssum[tid >> 5] = mysum;
    __syncthreads();
    if (tid == 0) {
        int s = 0;
#pragma unroll
        for (int i = 0; i < 8; i++) s += ssum[i];
        g_sw[n] = scale;
        g_sumw[n] = s;
    }
}

// ---------------- GEMM: IMMA mma.sync, 128x128 CTA, 64x32 warp, 4-stage -----
#define BM 128
#define BN 128
#define BKB 64                       // int8 K elems per stage
#define KT (K_DIM / BKB)             // 64
#define SA_OFF(s) ((s) * 8192)
#define SB_OFF(s) (32768 + (s) * 8192)
#define SMEM_BYTES 65536

__global__ __launch_bounds__(256, 1)
void gemm_kernel(const float* __restrict__ bias, float* __restrict__ out) {
    extern __shared__ unsigned char smem[];
    const int tid = threadIdx.x;
    const int wid = tid >> 5, lid = tid & 31;
    const int wm = wid >> 2, wn = wid & 3;        // 2 x 4 warp grid
    const int m0 = blockIdx.y * BM;
    const int n0 = blockIdx.x * BN;
    const int mtBase = m0 >> 4;                   // 16-row tile index
    const int ntBase = n0 >> 3;                   // 8-col tile index
    const uint32_t sbase = smem_u32(smem);

    int acc[4][4][4];
#pragma unroll
    for (int i = 0; i < 4; i++)
#pragma unroll
        for (int j = 0; j < 4; j++)
#pragma unroll
            for (int q = 0; q < 4; q++) acc[i][j][q] = 0;

    // stage loader: A = 2 x 4KB contiguous, B = 2 x 4KB contiguous
#define ISSUE_STAGE(KTGT)                                                        \
    do {                                                                         \
        int _s = (KTGT) & 3;                                                     \
        _Pragma("unroll")                                                        \
        for (int ks = 0; ks < 2; ks++) {                                         \
            size_t at = ((size_t)((KTGT) * 2 + ks) * (M_DIM / 16) + mtBase) * 512; \
            CP_ASYNC16(sbase + SA_OFF(_s) + ks * 4096 + tid * 16,                \
                       g_Aq + at + tid * 16);                                    \
            size_t bt = ((size_t)((KTGT) * 2 + ks) * (N_DIM / 8) + ntBase) * 256; \
            CP_ASYNC16(sbase + SB_OFF(_s) + ks * 4096 + tid * 16,                \
                       g_Bq + bt + tid * 16);                                    \
        }                                                                        \
    } while (0)

    ISSUE_STAGE(0); CP_COMMIT();
    ISSUE_STAGE(1); CP_COMMIT();
    ISSUE_STAGE(2); CP_COMMIT();

#pragma unroll 1
    for (int kt = 0; kt < KT; kt++) {
        CP_WAIT2();
        __syncthreads();
        if (kt + 3 < KT) ISSUE_STAGE(kt + 3);
        CP_COMMIT();

        const unsigned char* sA = smem + SA_OFF(kt & 3);
        const unsigned char* sB = smem + SB_OFF(kt & 3);
#pragma unroll
        for (int ks = 0; ks < 2; ks++) {
            uint4 af[4];
            uint2 bf[4];
#pragma unroll
            for (int i = 0; i < 4; i++)
                af[i] = *(const uint4*)(sA + ks * 4096 + (wm * 4 + i) * 512 + lid * 16);
#pragma unroll
            for (int j = 0; j < 4; j++)
                bf[j] = *(const uint2*)(sB + ks * 4096 + (wn * 4 + j) * 256 + lid * 8);
#pragma unroll
            for (int i = 0; i < 4; i++)
#pragma unroll
                for (int j = 0; j < 4; j++)
                    mma_u8s8(acc[i][j], (const unsigned*)&af[i], (const unsigned*)&bf[j]);
        }
    }

    // ---------------- epilogue: dequant + zp correction + bias ----------------
    const int g = lid >> 2, tig = lid & 3;
#pragma unroll
    for (int i = 0; i < 4; i++) {
        int r0 = m0 + wm * 64 + i * 16 + g;
        int r1 = r0 + 8;
        int zp0 = g_zp[r0], zp1 = g_zp[r1];
        float sa0 = g_sa[r0], sa1 = g_sa[r1];
#pragma unroll
        for (int j = 0; j < 4; j++) {
            int col = n0 + wn * 32 + j * 8 + tig * 2;
            int su0 = g_sumw[col], su1 = g_sumw[col + 1];
            float sw0 = g_sw[col], sw1 = g_sw[col + 1];
            float b0 = bias[col], b1 = bias[col + 1];
            float2 y0, y1;
            y0.x = (float)(acc[i][j][0] - zp0 * su0) * (sa0 * sw0) + b0;
            y0.y = (float)(acc[i][j][1] - zp0 * su1) * (sa0 * sw1) + b1;
            y1.x = (float)(acc[i][j][2] - zp1 * su0) * (sa1 * sw0) + b0;
            y1.y = (float)(acc[i][j][3] - zp1 * su1) * (sa1 * sw1) + b1;
            *(float2*)(out + (size_t)r0 * N_DIM + col) = y0;
            *(float2*)(out + (size_t)r1 * N_DIM + col) = y1;
        }
    }
}

// ---------------- launch -----------------------------------------------------
extern "C" void kernel_launch(void* const* d_in, const int* in_sizes, int n_in,
                              void* d_out, int out_size) {
    const float* x = (const float*)d_in[0];
    const float* w = (const float*)d_in[1];
    const float* bias = (const float*)d_in[2];
    float* out = (float*)d_out;

    cudaFuncSetAttribute(gemm_kernel, cudaFuncAttributeMaxDynamicSharedMemorySize,
                         SMEM_BYTES);

    quant_x_kernel<<<M_DIM, 256>>>(x);
    quant_w_kernel<<<N_DIM, 256>>>(w);
    dim3 grid(N_DIM / BN, M_DIM / BM);
    gemm_kernel<<<grid, 256, SMEM_BYTES>>>(bias, out);
}

// round 3
// speedup vs baseline: 2.3267x; 2.3267x over previous
#include <cuda_runtime.h>
#include <cuda_bf16.h>
#include <cstdint>

#define M_DIM 8192
#define N_DIM 4096
#define K_DIM 4096

// ---------------- scratch (device globals; no allocations allowed) ----------
// A packed as [K/16][M/16] tiles of 512B: 16x16 bf16 tile in m16n8k16 A-frag order.
// B packed as [K/16][N/8]  tiles of 256B: 16x8  bf16 tile in m16n8k16 B-frag order.
__device__ __align__(128) __nv_bfloat16 g_A[(size_t)M_DIM * K_DIM];
__device__ __align__(128) __nv_bfloat16 g_B[(size_t)N_DIM * K_DIM];
__device__ float g_sa[M_DIM];   // activation scale per token
__device__ float g_sw[N_DIM];   // weight scale per row

// ---------------- helpers ----------------------------------------------------
__device__ __forceinline__ uint32_t smem_u32(const void* p) {
    uint32_t a;
    asm("{ .reg .u64 t; cvta.to.shared.u64 t, %1; cvt.u32.u64 %0, t; }"
        : "=r"(a) : "l"(p));
    return a;
}

#define CP_ASYNC16(dst, src) \
    asm volatile("cp.async.cg.shared.global [%0], [%1], 16;" \
                 :: "r"(dst), "l"(src) : "memory")
#define CP_COMMIT() asm volatile("cp.async.commit_group;" ::: "memory")
#define CP_WAIT2()  asm volatile("cp.async.wait_group 2;" ::: "memory")

__device__ __forceinline__ void mma_bf16(float* d, const unsigned* a, const unsigned* b) {
    asm volatile(
        "mma.sync.aligned.m16n8k16.row.col.f32.bf16.bf16.f32 "
        "{%0,%1,%2,%3}, {%4,%5,%6,%7}, {%8,%9}, {%0,%1,%2,%3};"
        : "+f"(d[0]), "+f"(d[1]), "+f"(d[2]), "+f"(d[3])
        : "r"(a[0]), "r"(a[1]), "r"(a[2]), "r"(a[3]),
          "r"(b[0]), "r"(b[1]));
}

// ---------------- fused quantization + fragment packing ----------------------
// A elem (m,k): tile=(k>>4)*(M/16)+(m>>4); r=m&15,c=k&15;
//   lane=(r&7)*4+((c&7)>>1); reg=(r>=8)+2*(c>=8); byte=lane*16+reg*4+(c&1)*2
// B elem (n,k): tile=(k>>4)*(N/8)+(n>>3); g=n&7,kk=k&15;
//   lane=g*4+((kk&7)>>1); reg=(kk>=8); byte=lane*8+reg*4+(kk&1)*2
__device__ __forceinline__ void do_quant_x(const float* __restrict__ x, int m, int tid) {
    const float4* xr = (const float4*)(x + (size_t)m * K_DIM);
    float4 v[4];
    float mn = 3.4e38f, mx = -3.4e38f;
#pragma unroll
    for (int i = 0; i < 4; i++) {
        v[i] = xr[tid + i * 256];
        mn = fminf(mn, fminf(fminf(v[i].x, v[i].y), fminf(v[i].z, v[i].w)));
        mx = fmaxf(mx, fmaxf(fmaxf(v[i].x, v[i].y), fmaxf(v[i].z, v[i].w)));
    }
#pragma unroll
    for (int o = 16; o; o >>= 1) {
        mn = fminf(mn, __shfl_xor_sync(0xFFFFFFFFu, mn, o));
        mx = fmaxf(mx, __shfl_xor_sync(0xFFFFFFFFu, mx, o));
    }
    __shared__ float smn[8], smx[8];
    if ((tid & 31) == 0) { smn[tid >> 5] = mn; smx[tid >> 5] = mx; }
    __syncthreads();
    mn = smn[0]; mx = smx[0];
#pragma unroll
    for (int i = 1; i < 8; i++) { mn = fminf(mn, smn[i]); mx = fmaxf(mx, smx[i]); }

    float rng = mx - mn;
    float scale = (rng > 0.0f) ? rng * (1.0f / 255.0f) : 1.0f;
    float zpf = rintf(-mn / scale);
    if (tid == 0) g_sa[m] = scale;

    const int r = m & 15, mt = m >> 4;
    const uint32_t lr = (uint32_t)(r & 7) * 4;
    const uint32_t rhi = (r >= 8) ? 4u : 0u;       // reg*4 contribution of row-high
    float inv = 1.0f / scale;
    char* Ab = (char*)g_A;
#pragma unroll
    for (int i = 0; i < 4; i++) {
        int f = tid + i * 256;
        int kt = f >> 2;                 // k16 index
        int c = (f * 4) & 15;            // 0,4,8,12
        float q0 = fminf(fmaxf(rintf(v[i].x * inv) + zpf, 0.0f), 255.0f) - zpf;
        float q1 = fminf(fmaxf(rintf(v[i].y * inv) + zpf, 0.0f), 255.0f) - zpf;
        float q2 = fminf(fmaxf(rintf(v[i].z * inv) + zpf, 0.0f), 255.0f) - zpf;
        float q3 = fminf(fmaxf(rintf(v[i].w * inv) + zpf, 0.0f), 255.0f) - zpf;
        size_t tile = ((size_t)kt * (M_DIM / 16) + mt) * 512;
        // pair (c, c+1)
        uint32_t lane0 = lr + ((c & 7) >> 1);
        uint32_t off0 = lane0 * 16 + rhi + ((c >= 8) ? 8u : 0u);
        *(__nv_bfloat162*)(Ab + tile + off0) = __floats2bfloat162_rn(q0, q1);
        // pair (c+2, c+3)
        int c2 = c + 2;
        uint32_t lane1 = lr + ((c2 & 7) >> 1);
        uint32_t off1 = lane1 * 16 + rhi + ((c2 >= 8) ? 8u : 0u);
        *(__nv_bfloat162*)(Ab + tile + off1) = __floats2bfloat162_rn(q2, q3);
    }
}

__device__ __forceinline__ void do_quant_w(const float* __restrict__ w, int n, int tid) {
    const float4* wr = (const float4*)(w + (size_t)n * K_DIM);
    float4 v[4];
    float am = 0.0f;
#pragma unroll
    for (int i = 0; i < 4; i++) {
        v[i] = wr[tid + i * 256];
        am = fmaxf(am, fmaxf(fmaxf(fabsf(v[i].x), fabsf(v[i].y)),
                             fmaxf(fabsf(v[i].z), fabsf(v[i].w))));
    }
#pragma unroll
    for (int o = 16; o; o >>= 1)
        am = fmaxf(am, __shfl_xor_sync(0xFFFFFFFFu, am, o));
    __shared__ float sam[8];
    if ((tid & 31) == 0) sam[tid >> 5] = am;
    __syncthreads();
    am = sam[0];
#pragma unroll
    for (int i = 1; i < 8; i++) am = fmaxf(am, sam[i]);

    float scale = (am > 0.0f) ? am * (1.0f / 127.0f) : 1.0f;
    float inv = 1.0f / scale;
    if (tid == 0) g_sw[n] = scale;

    const int g = n & 7, nt = n >> 3;
    const uint32_t lg = (uint32_t)g * 4;
    char* Bb = (char*)g_B;
#pragma unroll
    for (int i = 0; i < 4; i++) {
        int f = tid + i * 256;
        int kt = f >> 2;
        int kk = (f * 4) & 15;           // 0,4,8,12
        float q0 = fminf(fmaxf(rintf(v[i].x * inv), -127.0f), 127.0f);
        float q1 = fminf(fmaxf(rintf(v[i].y * inv), -127.0f), 127.0f);
        float q2 = fminf(fmaxf(rintf(v[i].z * inv), -127.0f), 127.0f);
        float q3 = fminf(fmaxf(rintf(v[i].w * inv), -127.0f), 127.0f);
        size_t tile = ((size_t)kt * (N_DIM / 8) + nt) * 256;
        uint32_t lane0 = lg + ((kk & 7) >> 1);
        uint32_t off0 = lane0 * 8 + ((kk >= 8) ? 4u : 0u);
        *(__nv_bfloat162*)(Bb + tile + off0) = __floats2bfloat162_rn(q0, q1);
        int k2 = kk + 2;
        uint32_t lane1 = lg + ((k2 & 7) >> 1);
        uint32_t off1 = lane1 * 8 + ((k2 >= 8) ? 4u : 0u);
        *(__nv_bfloat162*)(Bb + tile + off1) = __floats2bfloat162_rn(q2, q3);
    }
}

__global__ __launch_bounds__(256) void quant_kernel(const float* __restrict__ x,
                                                    const float* __restrict__ w) {
    int bid = blockIdx.x;
    if (bid < M_DIM) do_quant_x(x, bid, threadIdx.x);
    else             do_quant_w(w, bid - M_DIM, threadIdx.x);
}

// ---------------- GEMM: bf16 HMMA, 128x128 CTA, 64x32 warp, 4-stage ---------
#define BM 128
#define BN 128
#define K16_PER_STAGE 4                 // BK = 64 bf16
#define KSTAGES (K_DIM / (16 * K16_PER_STAGE))   // 64
#define SA_OFF(s) ((s) * 32768)
#define SB_OFF(s) ((s) * 32768 + 16384)
#define SMEM_BYTES 131072

__global__ __launch_bounds__(256, 1)
void gemm_kernel(const float* __restrict__ bias, float* __restrict__ out) {
    extern __shared__ unsigned char smem[];
    const int tid = threadIdx.x;
    const int wid = tid >> 5, lid = tid & 31;
    const int wm = wid >> 2, wn = wid & 3;        // 2 x 4 warp grid
    const int m0 = blockIdx.y * BM;
    const int n0 = blockIdx.x * BN;
    const int mtBase = m0 >> 4;                   // 16-row tile index
    const int ntBase = n0 >> 3;                   // 8-col tile index
    const uint32_t sbase = smem_u32(smem);
    const char* Ab = (const char*)g_A;
    const char* Bb = (const char*)g_B;

    float acc[4][4][4];
#pragma unroll
    for (int i = 0; i < 4; i++)
#pragma unroll
        for (int j = 0; j < 4; j++)
#pragma unroll
            for (int q = 0; q < 4; q++) acc[i][j][q] = 0.0f;

#define ISSUE_STAGE(STG)                                                         \
    do {                                                                         \
        int _s = (STG) & 3;                                                      \
        _Pragma("unroll")                                                        \
        for (int kk = 0; kk < K16_PER_STAGE; kk++) {                             \
            int k16 = (STG) * K16_PER_STAGE + kk;                                \
            size_t at = ((size_t)k16 * (M_DIM / 16) + mtBase) * 512;             \
            CP_ASYNC16(sbase + SA_OFF(_s) + kk * 4096 + tid * 16,                \
                       Ab + at + tid * 16);                                      \
            size_t bt = ((size_t)k16 * (N_DIM / 8) + ntBase) * 256;              \
            CP_ASYNC16(sbase + SB_OFF(_s) + kk * 4096 + tid * 16,                \
                       Bb + bt + tid * 16);                                      \
        }                                                                        \
    } while (0)

    ISSUE_STAGE(0); CP_COMMIT();
    ISSUE_STAGE(1); CP_COMMIT();
    ISSUE_STAGE(2); CP_COMMIT();

#pragma unroll 1
    for (int st = 0; st < KSTAGES; st++) {
        CP_WAIT2();
        __syncthreads();
        if (st + 3 < KSTAGES) ISSUE_STAGE(st + 3);
        CP_COMMIT();

        const unsigned char* sA = smem + SA_OFF(st & 3);
        const unsigned char* sB = smem + SB_OFF(st & 3);
#pragma unroll
        for (int kk = 0; kk < K16_PER_STAGE; kk++) {
            uint4 af[4];
            uint2 bf[4];
#pragma unroll
            for (int i = 0; i < 4; i++)
                af[i] = *(const uint4*)(sA + kk * 4096 + (wm * 4 + i) * 512 + lid * 16);
#pragma unroll
            for (int j = 0; j < 4; j++)
                bf[j] = *(const uint2*)(sB + kk * 4096 + (wn * 4 + j) * 256 + lid * 8);
#pragma unroll
            for (int i = 0; i < 4; i++)
#pragma unroll
                for (int j = 0; j < 4; j++)
                    mma_bf16(acc[i][j], (const unsigned*)&af[i], (const unsigned*)&bf[j]);
        }
    }

    // ---------------- epilogue: dequant + bias --------------------------------
    const int g = lid >> 2, tig = lid & 3;
#pragma unroll
    for (int i = 0; i < 4; i++) {
        int r0 = m0 + wm * 64 + i * 16 + g;
        int r1 = r0 + 8;
        float sa0 = g_sa[r0], sa1 = g_sa[r1];
#pragma unroll
        for (int j = 0; j < 4; j++) {
            int col = n0 + wn * 32 + j * 8 + tig * 2;
            float sw0 = g_sw[col], sw1 = g_sw[col + 1];
            float b0 = bias[col], b1 = bias[col + 1];
            float2 y0, y1;
            y0.x = acc[i][j][0] * (sa0 * sw0) + b0;
            y0.y = acc[i][j][1] * (sa0 * sw1) + b1;
            y1.x = acc[i][j][2] * (sa1 * sw0) + b0;
            y1.y = acc[i][j][3] * (sa1 * sw1) + b1;
            *(float2*)(out + (size_t)r0 * N_DIM + col) = y0;
            *(float2*)(out + (size_t)r1 * N_DIM + col) = y1;
        }
    }
}

// ---------------- launch -----------------------------------------------------
extern "C" void kernel_launch(void* const* d_in, const int* in_sizes, int n_in,
                              void* d_out, int out_size) {
    const float* x = (const float*)d_in[0];
    const float* w = (const float*)d_in[1];
    const float* bias = (const float*)d_in[2];
    float* out = (float*)d_out;

    cudaFuncSetAttribute(gemm_kernel, cudaFuncAttributeMaxDynamicSharedMemorySize,
                         SMEM_BYTES);

    quant_kernel<<<M_DIM + N_DIM, 256>>>(x, w);
    dim3 grid(N_DIM / BN, M_DIM / BM);
    gemm_kernel<<<grid, 256, SMEM_BYTES>>>(bias, out);
}

// round 5
// speedup vs baseline: 2.7345x; 1.1753x over previous
#include <cuda_runtime.h>
#include <cuda_bf16.h>
#include <cstdint>

#define M_DIM 8192
#define N_DIM 4096
#define K_DIM 4096

// ---------------- scratch (device globals; no allocations allowed) ----------
// A packed as [K/16][M/16] tiles of 512B: 16x16 bf16 tile in m16n8k16 A-frag order.
// B packed as [K/16][N/8]  tiles of 256B: 16x8  bf16 tile in m16n8k16 B-frag order.
__device__ __align__(128) __nv_bfloat16 g_A[(size_t)M_DIM * K_DIM];
__device__ __align__(128) __nv_bfloat16 g_B[(size_t)N_DIM * K_DIM];
__device__ float g_sa[M_DIM];   // activation scale per token
__device__ float g_sw[N_DIM];   // weight scale per row

// ---------------- helpers ----------------------------------------------------
__device__ __forceinline__ uint32_t smem_u32(const void* p) {
    uint32_t a;
    asm("{ .reg .u64 t; cvta.to.shared.u64 t, %1; cvt.u32.u64 %0, t; }"
        : "=r"(a) : "l"(p));
    return a;
}

#define CP_ASYNC16(dst, src) \
    asm volatile("cp.async.cg.shared.global [%0], [%1], 16;" \
                 :: "r"(dst), "l"(src) : "memory")
#define CP_COMMIT() asm volatile("cp.async.commit_group;" ::: "memory")
#define CP_WAIT1()  asm volatile("cp.async.wait_group 1;" ::: "memory")

__device__ __forceinline__ void mma_bf16(float* d, const unsigned* a, const unsigned* b) {
    asm volatile(
        "mma.sync.aligned.m16n8k16.row.col.f32.bf16.bf16.f32 "
        "{%0,%1,%2,%3}, {%4,%5,%6,%7}, {%8,%9}, {%0,%1,%2,%3};"
        : "+f"(d[0]), "+f"(d[1]), "+f"(d[2]), "+f"(d[3])
        : "r"(a[0]), "r"(a[1]), "r"(a[2]), "r"(a[3]),
          "r"(b[0]), "r"(b[1]));
}

// ---------------- fused quantization + fragment packing ----------------------
// A elem (m,k): tile=(k>>4)*(M/16)+(m>>4); r=m&15,c=k&15;
//   lane=(r&7)*4+((c&7)>>1); reg=(r>=8)+2*(c>=8); byte=lane*16+reg*4+(c&1)*2
// B elem (n,k): tile=(k>>4)*(N/8)+(n>>3); g=n&7,kk=k&15;
//   lane=g*4+((kk&7)>>1); reg=(kk>=8); byte=lane*8+reg*4+(kk&1)*2
__device__ __forceinline__ void do_quant_x(const float* __restrict__ x, int m, int tid) {
    const float4* xr = (const float4*)(x + (size_t)m * K_DIM);
    float4 v[4];
    float mn = 3.4e38f, mx = -3.4e38f;
#pragma unroll
    for (int i = 0; i < 4; i++) {
        v[i] = xr[tid + i * 256];
        mn = fminf(mn, fminf(fminf(v[i].x, v[i].y), fminf(v[i].z, v[i].w)));
        mx = fmaxf(mx, fmaxf(fmaxf(v[i].x, v[i].y), fmaxf(v[i].z, v[i].w)));
    }
#pragma unroll
    for (int o = 16; o; o >>= 1) {
        mn = fminf(mn, __shfl_xor_sync(0xFFFFFFFFu, mn, o));
        mx = fmaxf(mx, __shfl_xor_sync(0xFFFFFFFFu, mx, o));
    }
    __shared__ float smn[8], smx[8];
    if ((tid & 31) == 0) { smn[tid >> 5] = mn; smx[tid >> 5] = mx; }
    __syncthreads();
    mn = smn[0]; mx = smx[0];
#pragma unroll
    for (int i = 1; i < 8; i++) { mn = fminf(mn, smn[i]); mx = fmaxf(mx, smx[i]); }

    float rng = mx - mn;
    float scale = (rng > 0.0f) ? rng * (1.0f / 255.0f) : 1.0f;
    float zpf = rintf(-mn / scale);
    if (tid == 0) g_sa[m] = scale;

    const int r = m & 15, mt = m >> 4;
    const uint32_t lr = (uint32_t)(r & 7) * 4;
    const uint32_t rhi = (r >= 8) ? 4u : 0u;
    float inv = 1.0f / scale;
    char* Ab = (char*)g_A;
#pragma unroll
    for (int i = 0; i < 4; i++) {
        int f = tid + i * 256;
        int kt = f >> 2;                 // k16 index
        int c = (f * 4) & 15;            // 0,4,8,12
        float q0 = fminf(fmaxf(rintf(v[i].x * inv) + zpf, 0.0f), 255.0f) - zpf;
        float q1 = fminf(fmaxf(rintf(v[i].y * inv) + zpf, 0.0f), 255.0f) - zpf;
        float q2 = fminf(fmaxf(rintf(v[i].z * inv) + zpf, 0.0f), 255.0f) - zpf;
        float q3 = fminf(fmaxf(rintf(v[i].w * inv) + zpf, 0.0f), 255.0f) - zpf;
        size_t tile = ((size_t)kt * (M_DIM / 16) + mt) * 512;
        uint32_t lane0 = lr + ((c & 7) >> 1);
        uint32_t off0 = lane0 * 16 + rhi + ((c >= 8) ? 8u : 0u);
        *(__nv_bfloat162*)(Ab + tile + off0) = __floats2bfloat162_rn(q0, q1);
        int c2 = c + 2;
        uint32_t lane1 = lr + ((c2 & 7) >> 1);
        uint32_t off1 = lane1 * 16 + rhi + ((c2 >= 8) ? 8u : 0u);
        *(__nv_bfloat162*)(Ab + tile + off1) = __floats2bfloat162_rn(q2, q3);
    }
}

__device__ __forceinline__ void do_quant_w(const float* __restrict__ w, int n, int tid) {
    const float4* wr = (const float4*)(w + (size_t)n * K_DIM);
    float4 v[4];
    float am = 0.0f;
#pragma unroll
    for (int i = 0; i < 4; i++) {
        v[i] = wr[tid + i * 256];
        am = fmaxf(am, fmaxf(fmaxf(fabsf(v[i].x), fabsf(v[i].y)),
                             fmaxf(fabsf(v[i].z), fabsf(v[i].w))));
    }
#pragma unroll
    for (int o = 16; o; o >>= 1)
        am = fmaxf(am, __shfl_xor_sync(0xFFFFFFFFu, am, o));
    __shared__ float sam[8];
    if ((tid & 31) == 0) sam[tid >> 5] = am;
    __syncthreads();
    am = sam[0];
#pragma unroll
    for (int i = 1; i < 8; i++) am = fmaxf(am, sam[i]);

    float scale = (am > 0.0f) ? am * (1.0f / 127.0f) : 1.0f;
    float inv = 1.0f / scale;
    if (tid == 0) g_sw[n] = scale;

    const int g = n & 7, nt = n >> 3;
    const uint32_t lg = (uint32_t)g * 4;
    char* Bb = (char*)g_B;
#pragma unroll
    for (int i = 0; i < 4; i++) {
        int f = tid + i * 256;
        int kt = f >> 2;
        int kk = (f * 4) & 15;           // 0,4,8,12
        float q0 = fminf(fmaxf(rintf(v[i].x * inv), -127.0f), 127.0f);
        float q1 = fminf(fmaxf(rintf(v[i].y * inv), -127.0f), 127.0f);
        float q2 = fminf(fmaxf(rintf(v[i].z * inv), -127.0f), 127.0f);
        float q3 = fminf(fmaxf(rintf(v[i].w * inv), -127.0f), 127.0f);
        size_t tile = ((size_t)kt * (N_DIM / 8) + nt) * 256;
        uint32_t lane0 = lg + ((kk & 7) >> 1);
        uint32_t off0 = lane0 * 8 + ((kk >= 8) ? 4u : 0u);
        *(__nv_bfloat162*)(Bb + tile + off0) = __floats2bfloat162_rn(q0, q1);
        int k2 = kk + 2;
        uint32_t lane1 = lg + ((k2 & 7) >> 1);
        uint32_t off1 = lane1 * 8 + ((k2 >= 8) ? 4u : 0u);
        *(__nv_bfloat162*)(Bb + tile + off1) = __floats2bfloat162_rn(q2, q3);
    }
}

__global__ __launch_bounds__(256) void quant_kernel(const float* __restrict__ x,
                                                    const float* __restrict__ w) {
    int bid = blockIdx.x;
    if (bid < M_DIM) do_quant_x(x, bid, threadIdx.x);
    else             do_quant_w(w, bid - M_DIM, threadIdx.x);
}

// ---------------- GEMM: bf16 HMMA, 128x128 CTA, 64x32 warp, 3-stage, 2 CTA/SM
#define BM 128
#define BN 128
#define K16_PER_STAGE 4                 // BK = 64 bf16
#define KSTAGES (K_DIM / (16 * K16_PER_STAGE))   // 64
#define SA_OFF(s) ((s) * 32768)
#define SB_OFF(s) ((s) * 32768 + 16384)
#define SMEM_BYTES 98304                // 3 stages x 32KB -> 2 CTAs/SM

__global__ __launch_bounds__(256, 2)
void gemm_kernel(const float* __restrict__ bias, float* __restrict__ out) {
    extern __shared__ unsigned char smem[];
    const int tid = threadIdx.x;
    const int wid = tid >> 5, lid = tid & 31;
    const int wm = wid >> 2, wn = wid & 3;        // 2 x 4 warp grid
    const int m0 = blockIdx.y * BM;
    const int n0 = blockIdx.x * BN;
    const int mtBase = m0 >> 4;
    const int ntBase = n0 >> 3;
    const uint32_t sbase = smem_u32(smem);
    const char* Ab = (const char*)g_A;
    const char* Bb = (const char*)g_B;

    float acc[4][4][4];
#pragma unroll
    for (int i = 0; i < 4; i++)
#pragma unroll
        for (int j = 0; j < 4; j++)
#pragma unroll
            for (int q = 0; q < 4; q++) acc[i][j][q] = 0.0f;

#define ISSUE_STAGE(STG)                                                         \
    do {                                                                         \
        int _s = (STG) % 3;                                                      \
        _Pragma("unroll")                                                        \
        for (int kk = 0; kk < K16_PER_STAGE; kk++) {                             \
            int k16 = (STG) * K16_PER_STAGE + kk;                                \
            size_t at = ((size_t)k16 * (M_DIM / 16) + mtBase) * 512;             \
            CP_ASYNC16(sbase + SA_OFF(_s) + kk * 4096 + tid * 16,                \
                       Ab + at + tid * 16);                                      \
            size_t bt = ((size_t)k16 * (N_DIM / 8) + ntBase) * 256;              \
            CP_ASYNC16(sbase + SB_OFF(_s) + kk * 4096 + tid * 16,                \
                       Bb + bt + tid * 16);                                      \
        }                                                                        \
    } while (0)

    ISSUE_STAGE(0); CP_COMMIT();
    ISSUE_STAGE(1); CP_COMMIT();

#pragma unroll 1
    for (int st = 0; st < KSTAGES; st++) {
        CP_WAIT1();
        __syncthreads();
        if (st + 2 < KSTAGES) { ISSUE_STAGE(st + 2); }
        CP_COMMIT();

        const unsigned char* sA = smem + SA_OFF(st % 3);
        const unsigned char* sB = smem + SB_OFF(st % 3);
#pragma unroll
        for (int kk = 0; kk < K16_PER_STAGE; kk++) {
            uint4 af[4];
            uint2 bf[4];
#pragma unroll
            for (int i = 0; i < 4; i++)
                af[i] = *(const uint4*)(sA + kk * 4096 + (wm * 4 + i) * 512 + lid * 16);
#pragma unroll
            for (int j = 0; j < 4; j++)
                bf[j] = *(const uint2*)(sB + kk * 4096 + (wn * 4 + j) * 256 + lid * 8);
#pragma unroll
            for (int i = 0; i < 4; i++)
#pragma unroll
                for (int j = 0; j < 4; j++)
                    mma_bf16(acc[i][j], (const unsigned*)&af[i], (const unsigned*)&bf[j]);
        }
    }

    // ---------------- epilogue: dequant + bias --------------------------------
    const int g = lid >> 2, tig = lid & 3;
#pragma unroll
    for (int i = 0; i < 4; i++) {
        int r0 = m0 + wm * 64 + i * 16 + g;
        int r1 = r0 + 8;
        float sa0 = g_sa[r0], sa1 = g_sa[r1];
#pragma unroll
        for (int j = 0; j < 4; j++) {
            int col = n0 + wn * 32 + j * 8 + tig * 2;
            float sw0 = g_sw[col], sw1 = g_sw[col + 1];
            float b0 = bias[col], b1 = bias[col + 1];
            float2 y0, y1;
            y0.x = acc[i][j][0] * (sa0 * sw0) + b0;
            y0.y = acc[i][j][1] * (sa0 * sw1) + b1;
            y1.x = acc[i][j][2] * (sa1 * sw0) + b0;
            y1.y = acc[i][j][3] * (sa1 * sw1) + b1;
            *(float2*)(out + (size_t)r0 * N_DIM + col) = y0;
            *(float2*)(out + (size_t)r1 * N_DIM + col) = y1;
        }
    }
}

// ---------------- launch -----------------------------------------------------
extern "C" void kernel_launch(void* const* d_in, const int* in_sizes, int n_in,
                              void* d_out, int out_size) {
    const float* x = (const float*)d_in[0];
    const float* w = (const float*)d_in[1];
    const float* bias = (const float*)d_in[2];
    float* out = (float*)d_out;

    cudaFuncSetAttribute(gemm_kernel, cudaFuncAttributeMaxDynamicSharedMemorySize,
                         SMEM_BYTES);

    quant_kernel<<<M_DIM + N_DIM, 256>>>(x, w);
    dim3 grid(N_DIM / BN, M_DIM / BM);
    gemm_kernel<<<grid, 256, SMEM_BYTES>>>(bias, out);
}

// round 6
// speedup vs baseline: 2.7644x; 1.0109x over previous
#include <cuda_runtime.h>
#include <cuda_bf16.h>
#include <cstdint>

#define M_DIM 8192
#define N_DIM 4096
#define K_DIM 4096

// ---------------- scratch (device globals; no allocations allowed) ----------
// A packed as [K/16][M/16] tiles of 512B: 16x16 bf16 tile in m16n8k16 A-frag order.
// B packed as [K/16][N/8]  tiles of 256B: 16x8  bf16 tile in m16n8k16 B-frag order.
__device__ __align__(128) __nv_bfloat16 g_A[(size_t)M_DIM * K_DIM];
__device__ __align__(128) __nv_bfloat16 g_B[(size_t)N_DIM * K_DIM];
__device__ float g_sa[M_DIM];   // activation scale per token
__device__ float g_sw[N_DIM];   // weight scale per row

// ---------------- helpers ----------------------------------------------------
__device__ __forceinline__ uint32_t smem_u32(const void* p) {
    uint32_t a;
    asm("{ .reg .u64 t; cvta.to.shared.u64 t, %1; cvt.u32.u64 %0, t; }"
        : "=r"(a) : "l"(p));
    return a;
}

#define CP_ASYNC16(dst, src) \
    asm volatile("cp.async.cg.shared.global [%0], [%1], 16;" \
                 :: "r"(dst), "l"(src) : "memory")
#define CP_COMMIT() asm volatile("cp.async.commit_group;" ::: "memory")
#define CP_WAIT1()  asm volatile("cp.async.wait_group 1;" ::: "memory")

__device__ __forceinline__ void mma_bf16(float* d, const unsigned* a, const unsigned* b) {
    asm volatile(
        "mma.sync.aligned.m16n8k16.row.col.f32.bf16.bf16.f32 "
        "{%0,%1,%2,%3}, {%4,%5,%6,%7}, {%8,%9}, {%0,%1,%2,%3};"
        : "+f"(d[0]), "+f"(d[1]), "+f"(d[2]), "+f"(d[3])
        : "r"(a[0]), "r"(a[1]), "r"(a[2]), "r"(a[3]),
          "r"(b[0]), "r"(b[1]));
}

// ---------------- fused quantization + fragment packing ----------------------
// A elem (m,k): tile=(k>>4)*(M/16)+(m>>4); r=m&15,c=k&15;
//   lane=(r&7)*4+((c&7)>>1); reg=(r>=8)+2*(c>=8); byte=lane*16+reg*4+(c&1)*2
// B elem (n,k): tile=(k>>4)*(N/8)+(n>>3); g=n&7,kk=k&15;
//   lane=g*4+((kk&7)>>1); reg=(kk>=8); byte=lane*8+reg*4+(kk&1)*2
__device__ __forceinline__ void do_quant_x(const float* __restrict__ x, int m, int tid) {
    const float4* xr = (const float4*)(x + (size_t)m * K_DIM);
    float4 v[4];
    float mn = 3.4e38f, mx = -3.4e38f;
#pragma unroll
    for (int i = 0; i < 4; i++) {
        v[i] = xr[tid + i * 256];
        mn = fminf(mn, fminf(fminf(v[i].x, v[i].y), fminf(v[i].z, v[i].w)));
        mx = fmaxf(mx, fmaxf(fmaxf(v[i].x, v[i].y), fmaxf(v[i].z, v[i].w)));
    }
#pragma unroll
    for (int o = 16; o; o >>= 1) {
        mn = fminf(mn, __shfl_xor_sync(0xFFFFFFFFu, mn, o));
        mx = fmaxf(mx, __shfl_xor_sync(0xFFFFFFFFu, mx, o));
    }
    __shared__ float smn[8], smx[8];
    if ((tid & 31) == 0) { smn[tid >> 5] = mn; smx[tid >> 5] = mx; }
    __syncthreads();
    mn = smn[0]; mx = smx[0];
#pragma unroll
    for (int i = 1; i < 8; i++) { mn = fminf(mn, smn[i]); mx = fmaxf(mx, smx[i]); }

    float rng = mx - mn;
    float scale = (rng > 0.0f) ? rng * (1.0f / 255.0f) : 1.0f;
    float zpf = rintf(-mn / scale);
    if (tid == 0) g_sa[m] = scale;

    const int r = m & 15, mt = m >> 4;
    const uint32_t lr = (uint32_t)(r & 7) * 4;
    const uint32_t rhi = (r >= 8) ? 4u : 0u;
    float inv = 1.0f / scale;
    char* Ab = (char*)g_A;
#pragma unroll
    for (int i = 0; i < 4; i++) {
        int f = tid + i * 256;
        int kt = f >> 2;                 // k16 index
        int c = (f * 4) & 15;            // 0,4,8,12
        float q0 = fminf(fmaxf(rintf(v[i].x * inv) + zpf, 0.0f), 255.0f) - zpf;
        float q1 = fminf(fmaxf(rintf(v[i].y * inv) + zpf, 0.0f), 255.0f) - zpf;
        float q2 = fminf(fmaxf(rintf(v[i].z * inv) + zpf, 0.0f), 255.0f) - zpf;
        float q3 = fminf(fmaxf(rintf(v[i].w * inv) + zpf, 0.0f), 255.0f) - zpf;
        size_t tile = ((size_t)kt * (M_DIM / 16) + mt) * 512;
        uint32_t lane0 = lr + ((c & 7) >> 1);
        uint32_t off0 = lane0 * 16 + rhi + ((c >= 8) ? 8u : 0u);
        *(__nv_bfloat162*)(Ab + tile + off0) = __floats2bfloat162_rn(q0, q1);
        int c2 = c + 2;
        uint32_t lane1 = lr + ((c2 & 7) >> 1);
        uint32_t off1 = lane1 * 16 + rhi + ((c2 >= 8) ? 8u : 0u);
        *(__nv_bfloat162*)(Ab + tile + off1) = __floats2bfloat162_rn(q2, q3);
    }
}

__device__ __forceinline__ void do_quant_w(const float* __restrict__ w, int n, int tid) {
    const float4* wr = (const float4*)(w + (size_t)n * K_DIM);
    float4 v[4];
    float am = 0.0f;
#pragma unroll
    for (int i = 0; i < 4; i++) {
        v[i] = wr[tid + i * 256];
        am = fmaxf(am, fmaxf(fmaxf(fabsf(v[i].x), fabsf(v[i].y)),
                             fmaxf(fabsf(v[i].z), fabsf(v[i].w))));
    }
#pragma unroll
    for (int o = 16; o; o >>= 1)
        am = fmaxf(am, __shfl_xor_sync(0xFFFFFFFFu, am, o));
    __shared__ float sam[8];
    if ((tid & 31) == 0) sam[tid >> 5] = am;
    __syncthreads();
    am = sam[0];
#pragma unroll
    for (int i = 1; i < 8; i++) am = fmaxf(am, sam[i]);

    float scale = (am > 0.0f) ? am * (1.0f / 127.0f) : 1.0f;
    float inv = 1.0f / scale;
    if (tid == 0) g_sw[n] = scale;

    const int g = n & 7, nt = n >> 3;
    const uint32_t lg = (uint32_t)g * 4;
    char* Bb = (char*)g_B;
#pragma unroll
    for (int i = 0; i < 4; i++) {
        int f = tid + i * 256;
        int kt = f >> 2;
        int kk = (f * 4) & 15;           // 0,4,8,12
        float q0 = fminf(fmaxf(rintf(v[i].x * inv), -127.0f), 127.0f);
        float q1 = fminf(fmaxf(rintf(v[i].y * inv), -127.0f), 127.0f);
        float q2 = fminf(fmaxf(rintf(v[i].z * inv), -127.0f), 127.0f);
        float q3 = fminf(fmaxf(rintf(v[i].w * inv), -127.0f), 127.0f);
        size_t tile = ((size_t)kt * (N_DIM / 8) + nt) * 256;
        uint32_t lane0 = lg + ((kk & 7) >> 1);
        uint32_t off0 = lane0 * 8 + ((kk >= 8) ? 4u : 0u);
        *(__nv_bfloat162*)(Bb + tile + off0) = __floats2bfloat162_rn(q0, q1);
        int k2 = kk + 2;
        uint32_t lane1 = lg + ((k2 & 7) >> 1);
        uint32_t off1 = lane1 * 8 + ((k2 >= 8) ? 4u : 0u);
        *(__nv_bfloat162*)(Bb + tile + off1) = __floats2bfloat162_rn(q2, q3);
    }
}

__global__ __launch_bounds__(256) void quant_kernel(const float* __restrict__ x,
                                                    const float* __restrict__ w) {
    int bid = blockIdx.x;
    if (bid < M_DIM) do_quant_x(x, bid, threadIdx.x);
    else             do_quant_w(w, bid - M_DIM, threadIdx.x);
}

// ---------------- GEMM: bf16 HMMA, 128x128 CTA, 64x32 warp, 3-stage, 2 CTA/SM
// cp.async for stage st+2 is spread across the 4 k16 compute chunks of stage st.
#define BM 128
#define BN 128
#define K16_PER_STAGE 4                 // BK = 64 bf16
#define KSTAGES (K_DIM / (16 * K16_PER_STAGE))   // 64
#define SA_OFF(s) ((s) * 32768)
#define SB_OFF(s) ((s) * 32768 + 16384)
#define SMEM_BYTES 98304                // 3 stages x 32KB -> 2 CTAs/SM

__global__ __launch_bounds__(256, 2)
void gemm_kernel(const float* __restrict__ bias, float* __restrict__ out) {
    extern __shared__ unsigned char smem[];
    const int tid = threadIdx.x;
    const int wid = tid >> 5, lid = tid & 31;
    const int wm = wid >> 2, wn = wid & 3;        // 2 x 4 warp grid
    const int m0 = blockIdx.y * BM;
    const int n0 = blockIdx.x * BN;
    const int mtBase = m0 >> 4;
    const int ntBase = n0 >> 3;
    const uint32_t sbase = smem_u32(smem);
    const char* Ab = (const char*)g_A;
    const char* Bb = (const char*)g_B;

    // per-thread gmem/smem offsets for the stage loader
    const uint32_t sA_my = (uint32_t)tid * 16;                 // within stage A region
    const uint32_t sB_my = (uint32_t)tid * 16;                 // within stage B region
    // per-warp smem fragment read offsets
    const uint32_t afro = (uint32_t)(wm * 4) * 512 + (uint32_t)lid * 16;
    const uint32_t bfro = (uint32_t)(wn * 4) * 256 + (uint32_t)lid * 8;

    float acc[4][4][4];
#pragma unroll
    for (int i = 0; i < 4; i++)
#pragma unroll
        for (int j = 0; j < 4; j++)
#pragma unroll
            for (int q = 0; q < 4; q++) acc[i][j][q] = 0.0f;

    // issue one k16 chunk (A 4KB + B 4KB) of stage STG into buffer s
#define ISSUE_CHUNK(STG, S, KKC)                                                 \
    do {                                                                         \
        int k16 = (STG) * K16_PER_STAGE + (KKC);                                 \
        size_t at = ((size_t)k16 * (M_DIM / 16) + mtBase) * 512;                 \
        CP_ASYNC16(sbase + SA_OFF(S) + (KKC) * 4096 + sA_my, Ab + at + sA_my);   \
        size_t bt = ((size_t)k16 * (N_DIM / 8) + ntBase) * 256;                  \
        CP_ASYNC16(sbase + SB_OFF(S) + (KKC) * 4096 + sB_my, Bb + bt + sB_my);   \
    } while (0)

    // prologue: stages 0 and 1 as whole groups
#pragma unroll
    for (int kk = 0; kk < K16_PER_STAGE; kk++) ISSUE_CHUNK(0, 0, kk);
    CP_COMMIT();
#pragma unroll
    for (int kk = 0; kk < K16_PER_STAGE; kk++) ISSUE_CHUNK(1, 1, kk);
    CP_COMMIT();

    int sread = 0, swrite = 2;
#pragma unroll 1
    for (int st = 0; st < KSTAGES; st++) {
        CP_WAIT1();               // stage st resident
        __syncthreads();

        const unsigned char* sA = smem + SA_OFF(sread);
        const unsigned char* sB = smem + SB_OFF(sread);
        const bool pf = (st + 2 < KSTAGES);

#pragma unroll
        for (int kk = 0; kk < K16_PER_STAGE; kk++) {
            // interleave next-next stage's loads with compute (2 cp.async/thread/chunk)
            if (pf) ISSUE_CHUNK(st + 2, swrite, kk);

            uint4 af[4];
            uint2 bf[4];
#pragma unroll
            for (int i = 0; i < 4; i++)
                af[i] = *(const uint4*)(sA + kk * 4096 + afro + i * 512);
#pragma unroll
            for (int j = 0; j < 4; j++)
                bf[j] = *(const uint2*)(sB + kk * 4096 + bfro + j * 256);
#pragma unroll
            for (int i = 0; i < 4; i++)
#pragma unroll
                for (int j = 0; j < 4; j++)
                    mma_bf16(acc[i][j], (const unsigned*)&af[i], (const unsigned*)&bf[j]);
        }
        CP_COMMIT();              // close stage st+2's group

        sread = (sread == 2) ? 0 : sread + 1;
        swrite = (swrite == 2) ? 0 : swrite + 1;
    }

    // ---------------- epilogue: dequant + bias --------------------------------
    const int g = lid >> 2, tig = lid & 3;
#pragma unroll
    for (int i = 0; i < 4; i++) {
        int r0 = m0 + wm * 64 + i * 16 + g;
        int r1 = r0 + 8;
        float sa0 = g_sa[r0], sa1 = g_sa[r1];
#pragma unroll
        for (int j = 0; j < 4; j++) {
            int col = n0 + wn * 32 + j * 8 + tig * 2;
            float sw0 = g_sw[col], sw1 = g_sw[col + 1];
            float b0 = bias[col], b1 = bias[col + 1];
            float2 y0, y1;
            y0.x = acc[i][j][0] * (sa0 * sw0) + b0;
            y0.y = acc[i][j][1] * (sa0 * sw1) + b1;
            y1.x = acc[i][j][2] * (sa1 * sw0) + b0;
            y1.y = acc[i][j][3] * (sa1 * sw1) + b1;
            *(float2*)(out + (size_t)r0 * N_DIM + col) = y0;
            *(float2*)(out + (size_t)r1 * N_DIM + col) = y1;
        }
    }
}

// ---------------- launch -----------------------------------------------------
extern "C" void kernel_launch(void* const* d_in, const int* in_sizes, int n_in,
                              void* d_out, int out_size) {
    const float* x = (const float*)d_in[0];
    const float* w = (const float*)d_in[1];
    const float* bias = (const float*)d_in[2];
    float* out = (float*)d_out;

    cudaFuncSetAttribute(gemm_kernel, cudaFuncAttributeMaxDynamicSharedMemorySize,
                         SMEM_BYTES);

    quant_kernel<<<M_DIM + N_DIM, 256>>>(x, w);
    dim3 grid(N_DIM / BN, M_DIM / BM);
    gemm_kernel<<<grid, 256, SMEM_BYTES>>>(bias, out);
}

// round 9
// speedup vs baseline: 2.8409x; 1.0277x over previous
#include <cuda_runtime.h>
#include <cuda_bf16.h>
#include <cstdint>

#define M_DIM 8192
#define N_DIM 4096
#define K_DIM 4096

// ---------------- scratch (device globals; no allocations allowed) ----------
// A packed as [K/16][M/16] tiles of 512B: 16x16 bf16 tile in m16n8k16 A-frag order.
// B packed as [K/16][N/8]  tiles of 256B: 16x8  bf16 tile in m16n8k16 B-frag order.
__device__ __align__(128) __nv_bfloat16 g_A[(size_t)M_DIM * K_DIM];
__device__ __align__(128) __nv_bfloat16 g_B[(size_t)N_DIM * K_DIM];
__device__ float g_sa[M_DIM];   // activation scale per token
__device__ float g_sw[N_DIM];   // weight scale per row

// ---------------- helpers ----------------------------------------------------
__device__ __forceinline__ uint32_t smem_u32(const void* p) {
    uint32_t a;
    asm("{ .reg .u64 t; cvta.to.shared.u64 t, %1; cvt.u32.u64 %0, t; }"
        : "=r"(a) : "l"(p));
    return a;
}

#define CP_ASYNC16(dst, src) \
    asm volatile("cp.async.cg.shared.global [%0], [%1], 16;" \
                 :: "r"(dst), "l"(src) : "memory")
#define CP_COMMIT() asm volatile("cp.async.commit_group;" ::: "memory")
#define CP_WAIT1()  asm volatile("cp.async.wait_group 1;" ::: "memory")

__device__ __forceinline__ void mma_bf16(float* d, const unsigned* a, const unsigned* b) {
    asm volatile(
        "mma.sync.aligned.m16n8k16.row.col.f32.bf16.bf16.f32 "
        "{%0,%1,%2,%3}, {%4,%5,%6,%7}, {%8,%9}, {%0,%1,%2,%3};"
        : "+f"(d[0]), "+f"(d[1]), "+f"(d[2]), "+f"(d[3])
        : "r"(a[0]), "r"(a[1]), "r"(a[2]), "r"(a[3]),
          "r"(b[0]), "r"(b[1]));
}

// ---------------- fused quantization + fragment packing ----------------------
// A elem (m,k): tile=(k>>4)*(M/16)+(m>>4); r=m&15,c=k&15;
//   lane=(r&7)*4+((c&7)>>1); reg=(r>=8)+2*(c>=8); byte=lane*16+reg*4+(c&1)*2
// B elem (n,k): tile=(k>>4)*(N/8)+(n>>3); g=n&7,kk=k&15;
//   lane=g*4+((kk&7)>>1); reg=(kk>=8); byte=lane*8+reg*4+(kk&1)*2
__device__ __forceinline__ void do_quant_x(const float* __restrict__ x, int m, int tid) {
    const float4* xr = (const float4*)(x + (size_t)m * K_DIM);
    float4 v[4];
    float mn = 3.4e38f, mx = -3.4e38f;
#pragma unroll
    for (int i = 0; i < 4; i++) {
        v[i] = xr[tid + i * 256];
        mn = fminf(mn, fminf(fminf(v[i].x, v[i].y), fminf(v[i].z, v[i].w)));
        mx = fmaxf(mx, fmaxf(fmaxf(v[i].x, v[i].y), fmaxf(v[i].z, v[i].w)));
    }
#pragma unroll
    for (int o = 16; o; o >>= 1) {
        mn = fminf(mn, __shfl_xor_sync(0xFFFFFFFFu, mn, o));
        mx = fmaxf(mx, __shfl_xor_sync(0xFFFFFFFFu, mx, o));
    }
    __shared__ float smn[8], smx[8];
    if ((tid & 31) == 0) { smn[tid >> 5] = mn; smx[tid >> 5] = mx; }
    __syncthreads();
    mn = smn[0]; mx = smx[0];
#pragma unroll
    for (int i = 1; i < 8; i++) { mn = fminf(mn, smn[i]); mx = fmaxf(mx, smx[i]); }

    float rng = mx - mn;
    float scale = (rng > 0.0f) ? rng * (1.0f / 255.0f) : 1.0f;
    float zpf = rintf(-mn / scale);
    if (tid == 0) g_sa[m] = scale;

    const int r = m & 15, mt = m >> 4;
    const uint32_t lr = (uint32_t)(r & 7) * 4;
    const uint32_t rhi = (r >= 8) ? 4u : 0u;
    float inv = 1.0f / scale;
    char* Ab = (char*)g_A;
#pragma unroll
    for (int i = 0; i < 4; i++) {
        int f = tid + i * 256;
        int kt = f >> 2;                 // k16 index
        int c = (f * 4) & 15;            // 0,4,8,12
        float q0 = fminf(fmaxf(rintf(v[i].x * inv) + zpf, 0.0f), 255.0f) - zpf;
        float q1 = fminf(fmaxf(rintf(v[i].y * inv) + zpf, 0.0f), 255.0f) - zpf;
        float q2 = fminf(fmaxf(rintf(v[i].z * inv) + zpf, 0.0f), 255.0f) - zpf;
        float q3 = fminf(fmaxf(rintf(v[i].w * inv) + zpf, 0.0f), 255.0f) - zpf;
        size_t tile = ((size_t)kt * (M_DIM / 16) + mt) * 512;
        uint32_t lane0 = lr + ((c & 7) >> 1);
        uint32_t off0 = lane0 * 16 + rhi + ((c >= 8) ? 8u : 0u);
        *(__nv_bfloat162*)(Ab + tile + off0) = __floats2bfloat162_rn(q0, q1);
        int c2 = c + 2;
        uint32_t lane1 = lr + ((c2 & 7) >> 1);
        uint32_t off1 = lane1 * 16 + rhi + ((c2 >= 8) ? 8u : 0u);
        *(__nv_bfloat162*)(Ab + tile + off1) = __floats2bfloat162_rn(q2, q3);
    }
}

__device__ __forceinline__ void do_quant_w(const float* __restrict__ w, int n, int tid) {
    const float4* wr = (const float4*)(w + (size_t)n * K_DIM);
    float4 v[4];
    float am = 0.0f;
#pragma unroll
    for (int i = 0; i < 4; i++) {
        v[i] = wr[tid + i * 256];
        am = fmaxf(am, fmaxf(fmaxf(fabsf(v[i].x), fabsf(v[i].y)),
                             fmaxf(fabsf(v[i].z), fabsf(v[i].w))));
    }
#pragma unroll
    for (int o = 16; o; o >>= 1)
        am = fmaxf(am, __shfl_xor_sync(0xFFFFFFFFu, am, o));
    __shared__ float sam[8];
    if ((tid & 31) == 0) sam[tid >> 5] = am;
    __syncthreads();
    am = sam[0];
#pragma unroll
    for (int i = 1; i < 8; i++) am = fmaxf(am, sam[i]);

    float scale = (am > 0.0f) ? am * (1.0f / 127.0f) : 1.0f;
    float inv = 1.0f / scale;
    if (tid == 0) g_sw[n] = scale;

    const int g = n & 7, nt = n >> 3;
    const uint32_t lg = (uint32_t)g * 4;
    char* Bb = (char*)g_B;
#pragma unroll
    for (int i = 0; i < 4; i++) {
        int f = tid + i * 256;
        int kt = f >> 2;
        int kk = (f * 4) & 15;           // 0,4,8,12
        float q0 = fminf(fmaxf(rintf(v[i].x * inv), -127.0f), 127.0f);
        float q1 = fminf(fmaxf(rintf(v[i].y * inv), -127.0f), 127.0f);
        float q2 = fminf(fmaxf(rintf(v[i].z * inv), -127.0f), 127.0f);
        float q3 = fminf(fmaxf(rintf(v[i].w * inv), -127.0f), 127.0f);
        size_t tile = ((size_t)kt * (N_DIM / 8) + nt) * 256;
        uint32_t lane0 = lg + ((kk & 7) >> 1);
        uint32_t off0 = lane0 * 8 + ((kk >= 8) ? 4u : 0u);
        *(__nv_bfloat162*)(Bb + tile + off0) = __floats2bfloat162_rn(q0, q1);
        int k2 = kk + 2;
        uint32_t lane1 = lg + ((k2 & 7) >> 1);
        uint32_t off1 = lane1 * 8 + ((k2 >= 8) ? 4u : 0u);
        *(__nv_bfloat162*)(Bb + tile + off1) = __floats2bfloat162_rn(q2, q3);
    }
}

__global__ __launch_bounds__(256) void quant_kernel(const float* __restrict__ x,
                                                    const float* __restrict__ w) {
    int bid = blockIdx.x;
    if (bid < M_DIM) do_quant_x(x, bid, threadIdx.x);
    else             do_quant_w(w, bid - M_DIM, threadIdx.x);
}

// ---- GEMM: bf16 HMMA, 128x256 CTA, 8 warps of 64x64, 3-stage, 1 CTA/SM -----
#define BM 128
#define BN 256
#define K16_PER_STAGE 4                 // BK = 64 bf16
#define KSTAGES (K_DIM / (16 * K16_PER_STAGE))   // 64
#define STAGE_BYTES 49152               // A 16KB + B 32KB
#define SA_OFF(s) ((s) * STAGE_BYTES)
#define SB_OFF(s) ((s) * STAGE_BYTES + 16384)
#define SMEM_BYTES (3 * STAGE_BYTES)    // 144 KB

__global__ __launch_bounds__(256, 1)
void gemm_kernel(const float* __restrict__ bias, float* __restrict__ out) {
    extern __shared__ unsigned char smem[];
    const int tid = threadIdx.x;
    const int wid = tid >> 5, lid = tid & 31;
    const int wm = wid >> 2, wn = wid & 3;        // 2 x 4 warp grid, 64x64 tiles
    const int m0 = blockIdx.y * BM;
    const int n0 = blockIdx.x * BN;
    const int mtBase = m0 >> 4;                   // 8 A-tiles per k16
    const int ntBase = n0 >> 3;                   // 32 B-tiles per k16
    const uint32_t sbase = smem_u32(smem);
    const char* Ab = (const char*)g_A;
    const char* Bb = (const char*)g_B;

    const uint32_t my16 = (uint32_t)tid * 16;
    // per-warp smem fragment read offsets
    const uint32_t afro = (uint32_t)(wm * 4) * 512 + (uint32_t)lid * 16;
    const uint32_t bfro = (uint32_t)(wn * 8) * 256 + (uint32_t)lid * 8;

    float acc[4][8][4];
#pragma unroll
    for (int i = 0; i < 4; i++)
#pragma unroll
        for (int j = 0; j < 8; j++)
#pragma unroll
            for (int q = 0; q < 4; q++) acc[i][j][q] = 0.0f;

    // issue one k16 chunk (A 4KB + B 8KB) of stage STG into buffer S
#define ISSUE_CHUNK(STG, S, KKC)                                                 \
    do {                                                                         \
        int k16 = (STG) * K16_PER_STAGE + (KKC);                                 \
        size_t at = ((size_t)k16 * (M_DIM / 16) + mtBase) * 512;                 \
        CP_ASYNC16(sbase + SA_OFF(S) + (KKC) * 4096 + my16, Ab + at + my16);     \
        size_t bt = ((size_t)k16 * (N_DIM / 8) + ntBase) * 256;                  \
        CP_ASYNC16(sbase + SB_OFF(S) + (KKC) * 8192 + my16, Bb + bt + my16);     \
        CP_ASYNC16(sbase + SB_OFF(S) + (KKC) * 8192 + 4096 + my16,               \
                   Bb + bt + 4096 + my16);                                       \
    } while (0)

#pragma unroll
    for (int kk = 0; kk < K16_PER_STAGE; kk++) ISSUE_CHUNK(0, 0, kk);
    CP_COMMIT();
#pragma unroll
    for (int kk = 0; kk < K16_PER_STAGE; kk++) ISSUE_CHUNK(1, 1, kk);
    CP_COMMIT();

    int sread = 0, swrite = 2;
#pragma unroll 1
    for (int st = 0; st < KSTAGES; st++) {
        CP_WAIT1();               // stage st resident
        __syncthreads();

        const unsigned char* sA = smem + SA_OFF(sread);
        const unsigned char* sB = smem + SB_OFF(sread);
        const bool pf = (st + 2 < KSTAGES);

#pragma unroll
        for (int kk = 0; kk < K16_PER_STAGE; kk++) {
            if (pf) ISSUE_CHUNK(st + 2, swrite, kk);   // 3 cp.async interleaved

            uint4 af[4];
            uint2 bf[8];
#pragma unroll
            for (int i = 0; i < 4; i++)
                af[i] = *(const uint4*)(sA + kk * 4096 + afro + i * 512);
#pragma unroll
            for (int j = 0; j < 8; j++)
                bf[j] = *(const uint2*)(sB + kk * 8192 + bfro + j * 256);
#pragma unroll
            for (int i = 0; i < 4; i++)
#pragma unroll
                for (int j = 0; j < 8; j++)
                    mma_bf16(acc[i][j], (const unsigned*)&af[i], (const unsigned*)&bf[j]);
        }
        CP_COMMIT();

        sread = (sread == 2) ? 0 : sread + 1;
        swrite = (swrite == 2) ? 0 : swrite + 1;
    }

    // ---------------- epilogue: dequant + bias --------------------------------
    const int g = lid >> 2, tig = lid & 3;
#pragma unroll
    for (int i = 0; i < 4; i++) {
        int r0 = m0 + wm * 64 + i * 16 + g;
        int r1 = r0 + 8;
        float sa0 = g_sa[r0], sa1 = g_sa[r1];
#pragma unroll
        for (int j = 0; j < 8; j++) {
            int col = n0 + wn * 64 + j * 8 + tig * 2;
            float sw0 = g_sw[col], sw1 = g_sw[col + 1];
            float b0 = bias[col], b1 = bias[col + 1];
            float2 y0, y1;
            y0.x = acc[i][j][0] * (sa0 * sw0) + b0;
            y0.y = acc[i][j][1] * (sa0 * sw1) + b1;
            y1.x = acc[i][j][2] * (sa1 * sw0) + b0;
            y1.y = acc[i][j][3] * (sa1 * sw1) + b1;
            *(float2*)(out + (size_t)r0 * N_DIM + col) = y0;
            *(float2*)(out + (size_t)r1 * N_DIM + col) = y1;
        }
    }
}

// ---------------- launch -----------------------------------------------------
extern "C" void kernel_launch(void* const* d_in, const int* in_sizes, int n_in,
                              void* d_out, int out_size) {
    const float* x = (const float*)d_in[0];
    const float* w = (const float*)d_in[1];
    const float* bias = (const float*)d_in[2];
    float* out = (float*)d_out;

    cudaFuncSetAttribute(gemm_kernel, cudaFuncAttributeMaxDynamicSharedMemorySize,
                         SMEM_BYTES);

    quant_kernel<<<M_DIM + N_DIM, 256>>>(x, w);
    dim3 grid(N_DIM / BN, M_DIM / BM);
    gemm_kernel<<<grid, 256, SMEM_BYTES>>>(bias, out);
}

// round 10
// speedup vs baseline: 3.0191x; 1.0627x over previous
#include <cuda_runtime.h>
#include <cuda_bf16.h>
#include <cstdint>

#define M_DIM 8192
#define N_DIM 4096
#define K_DIM 4096

// ---------------- scratch (device globals; no allocations allowed) ----------
// A packed as [K/16][M/16] tiles of 512B: 16x16 bf16 tile in m16n8k16 A-frag order.
// B packed as [K/16][N/8]  tiles of 256B: 16x8  bf16 tile in m16n8k16 B-frag order.
__device__ __align__(128) __nv_bfloat16 g_A[(size_t)M_DIM * K_DIM];
__device__ __align__(128) __nv_bfloat16 g_B[(size_t)N_DIM * K_DIM];
__device__ float g_sa[M_DIM];   // activation scale per token
__device__ float g_sw[N_DIM];   // weight scale per row

// ---------------- helpers ----------------------------------------------------
__device__ __forceinline__ uint32_t smem_u32(const void* p) {
    uint32_t a;
    asm("{ .reg .u64 t; cvta.to.shared.u64 t, %1; cvt.u32.u64 %0, t; }"
        : "=r"(a) : "l"(p));
    return a;
}

#define CP_ASYNC16(dst, src) \
    asm volatile("cp.async.cg.shared.global [%0], [%1], 16;" \
                 :: "r"(dst), "l"(src) : "memory")
#define CP_COMMIT() asm volatile("cp.async.commit_group;" ::: "memory")
#define CP_WAIT0()  asm volatile("cp.async.wait_group 0;" ::: "memory")

__device__ __forceinline__ void mma_bf16(float* d, const unsigned* a, const unsigned* b) {
    asm volatile(
        "mma.sync.aligned.m16n8k16.row.col.f32.bf16.bf16.f32 "
        "{%0,%1,%2,%3}, {%4,%5,%6,%7}, {%8,%9}, {%0,%1,%2,%3};"
        : "+f"(d[0]), "+f"(d[1]), "+f"(d[2]), "+f"(d[3])
        : "r"(a[0]), "r"(a[1]), "r"(a[2]), "r"(a[3]),
          "r"(b[0]), "r"(b[1]));
}

// ---------------- fused quantization + fragment packing ----------------------
// A elem (m,k): tile=(k>>4)*(M/16)+(m>>4); r=m&15,c=k&15;
//   lane=(r&7)*4+((c&7)>>1); reg=(r>=8)+2*(c>=8); byte=lane*16+reg*4+(c&1)*2
// B elem (n,k): tile=(k>>4)*(N/8)+(n>>3); g=n&7,kk=k&15;
//   lane=g*4+((kk&7)>>1); reg=(kk>=8); byte=lane*8+reg*4+(kk&1)*2
__device__ __forceinline__ void do_quant_x(const float* __restrict__ x, int m, int tid) {
    const float4* xr = (const float4*)(x + (size_t)m * K_DIM);
    float4 v[4];
    float mn = 3.4e38f, mx = -3.4e38f;
#pragma unroll
    for (int i = 0; i < 4; i++) {
        v[i] = xr[tid + i * 256];
        mn = fminf(mn, fminf(fminf(v[i].x, v[i].y), fminf(v[i].z, v[i].w)));
        mx = fmaxf(mx, fmaxf(fmaxf(v[i].x, v[i].y), fmaxf(v[i].z, v[i].w)));
    }
#pragma unroll
    for (int o = 16; o; o >>= 1) {
        mn = fminf(mn, __shfl_xor_sync(0xFFFFFFFFu, mn, o));
        mx = fmaxf(mx, __shfl_xor_sync(0xFFFFFFFFu, mx, o));
    }
    __shared__ float smn[8], smx[8];
    if ((tid & 31) == 0) { smn[tid >> 5] = mn; smx[tid >> 5] = mx; }
    __syncthreads();
    mn = smn[0]; mx = smx[0];
#pragma unroll
    for (int i = 1; i < 8; i++) { mn = fminf(mn, smn[i]); mx = fmaxf(mx, smx[i]); }

    float rng = mx - mn;
    float scale = (rng > 0.0f) ? rng * (1.0f / 255.0f) : 1.0f;
    float zpf = rintf(-mn / scale);
    if (tid == 0) g_sa[m] = scale;

    const int r = m & 15, mt = m >> 4;
    const uint32_t lr = (uint32_t)(r & 7) * 4;
    const uint32_t rhi = (r >= 8) ? 4u : 0u;
    float inv = 1.0f / scale;
    char* Ab = (char*)g_A;
#pragma unroll
    for (int i = 0; i < 4; i++) {
        int f = tid + i * 256;
        int kt = f >> 2;                 // k16 index
        int c = (f * 4) & 15;            // 0,4,8,12
        float q0 = fminf(fmaxf(rintf(v[i].x * inv) + zpf, 0.0f), 255.0f) - zpf;
        float q1 = fminf(fmaxf(rintf(v[i].y * inv) + zpf, 0.0f), 255.0f) - zpf;
        float q2 = fminf(fmaxf(rintf(v[i].z * inv) + zpf, 0.0f), 255.0f) - zpf;
        float q3 = fminf(fmaxf(rintf(v[i].w * inv) + zpf, 0.0f), 255.0f) - zpf;
        size_t tile = ((size_t)kt * (M_DIM / 16) + mt) * 512;
        uint32_t lane0 = lr + ((c & 7) >> 1);
        uint32_t off0 = lane0 * 16 + rhi + ((c >= 8) ? 8u : 0u);
        *(__nv_bfloat162*)(Ab + tile + off0) = __floats2bfloat162_rn(q0, q1);
        int c2 = c + 2;
        uint32_t lane1 = lr + ((c2 & 7) >> 1);
        uint32_t off1 = lane1 * 16 + rhi + ((c2 >= 8) ? 8u : 0u);
        *(__nv_bfloat162*)(Ab + tile + off1) = __floats2bfloat162_rn(q2, q3);
    }
}

__device__ __forceinline__ void do_quant_w(const float* __restrict__ w, int n, int tid) {
    const float4* wr = (const float4*)(w + (size_t)n * K_DIM);
    float4 v[4];
    float am = 0.0f;
#pragma unroll
    for (int i = 0; i < 4; i++) {
        v[i] = wr[tid + i * 256];
        am = fmaxf(am, fmaxf(fmaxf(fabsf(v[i].x), fabsf(v[i].y)),
                             fmaxf(fabsf(v[i].z), fabsf(v[i].w))));
    }
#pragma unroll
    for (int o = 16; o; o >>= 1)
        am = fmaxf(am, __shfl_xor_sync(0xFFFFFFFFu, am, o));
    __shared__ float sam[8];
    if ((tid & 31) == 0) sam[tid >> 5] = am;
    __syncthreads();
    am = sam[0];
#pragma unroll
    for (int i = 1; i < 8; i++) am = fmaxf(am, sam[i]);

    float scale = (am > 0.0f) ? am * (1.0f / 127.0f) : 1.0f;
    float inv = 1.0f / scale;
    if (tid == 0) g_sw[n] = scale;

    const int g = n & 7, nt = n >> 3;
    const uint32_t lg = (uint32_t)g * 4;
    char* Bb = (char*)g_B;
#pragma unroll
    for (int i = 0; i < 4; i++) {
        int f = tid + i * 256;
        int kt = f >> 2;
        int kk = (f * 4) & 15;           // 0,4,8,12
        float q0 = fminf(fmaxf(rintf(v[i].x * inv), -127.0f), 127.0f);
        float q1 = fminf(fmaxf(rintf(v[i].y * inv), -127.0f), 127.0f);
        float q2 = fminf(fmaxf(rintf(v[i].z * inv), -127.0f), 127.0f);
        float q3 = fminf(fmaxf(rintf(v[i].w * inv), -127.0f), 127.0f);
        size_t tile = ((size_t)kt * (N_DIM / 8) + nt) * 256;
        uint32_t lane0 = lg + ((kk & 7) >> 1);
        uint32_t off0 = lane0 * 8 + ((kk >= 8) ? 4u : 0u);
        *(__nv_bfloat162*)(Bb + tile + off0) = __floats2bfloat162_rn(q0, q1);
        int k2 = kk + 2;
        uint32_t lane1 = lg + ((k2 & 7) >> 1);
        uint32_t off1 = lane1 * 8 + ((k2 >= 8) ? 4u : 0u);
        *(__nv_bfloat162*)(Bb + tile + off1) = __floats2bfloat162_rn(q2, q3);
    }
}

__global__ __launch_bounds__(256) void quant_kernel(const float* __restrict__ x,
                                                    const float* __restrict__ w) {
    int bid = blockIdx.x;
    if (bid < M_DIM) do_quant_x(x, bid, threadIdx.x);
    else             do_quant_w(w, bid - M_DIM, threadIdx.x);
}

// ---- GEMM: bf16 HMMA, 128x256 CTA, 8 warps of 64x64, BK=128, 2-stage -------
#define BM 128
#define BN 256
#define K16_PER_STAGE 8                 // BK = 128 bf16
#define KSTAGES (K_DIM / (16 * K16_PER_STAGE))   // 32
#define STAGE_BYTES 98304               // A 32KB + B 64KB
#define SA_OFF(s) ((s) * STAGE_BYTES)
#define SB_OFF(s) ((s) * STAGE_BYTES + 32768)
#define SMEM_BYTES (2 * STAGE_BYTES)    // 192 KB

__global__ __launch_bounds__(256, 1)
void gemm_kernel(const float* __restrict__ bias, float* __restrict__ out) {
    extern __shared__ unsigned char smem[];
    const int tid = threadIdx.x;
    const int wid = tid >> 5, lid = tid & 31;
    const int wm = wid >> 2, wn = wid & 3;        // 2 x 4 warp grid, 64x64 tiles
    const int m0 = blockIdx.y * BM;
    const int n0 = blockIdx.x * BN;
    const int mtBase = m0 >> 4;                   // 8 A-tiles per k16
    const int ntBase = n0 >> 3;                   // 32 B-tiles per k16
    const uint32_t sbase = smem_u32(smem);
    const char* Ab = (const char*)g_A;
    const char* Bb = (const char*)g_B;

    const uint32_t my16 = (uint32_t)tid * 16;
    // per-warp smem fragment read offsets
    const uint32_t afro = (uint32_t)(wm * 4) * 512 + (uint32_t)lid * 16;
    const uint32_t bfro = (uint32_t)(wn * 8) * 256 + (uint32_t)lid * 8;

    float acc[4][8][4];
#pragma unroll
    for (int i = 0; i < 4; i++)
#pragma unroll
        for (int j = 0; j < 8; j++)
#pragma unroll
            for (int q = 0; q < 4; q++) acc[i][j][q] = 0.0f;

    // issue one k16 chunk (A 4KB + B 8KB) of stage STG into buffer S
#define ISSUE_CHUNK(STG, S, KKC)                                                 \
    do {                                                                         \
        int k16 = (STG) * K16_PER_STAGE + (KKC);                                 \
        size_t at = ((size_t)k16 * (M_DIM / 16) + mtBase) * 512;                 \
        CP_ASYNC16(sbase + SA_OFF(S) + (KKC) * 4096 + my16, Ab + at + my16);     \
        size_t bt = ((size_t)k16 * (N_DIM / 8) + ntBase) * 256;                  \
        CP_ASYNC16(sbase + SB_OFF(S) + (KKC) * 8192 + my16, Bb + bt + my16);     \
        CP_ASYNC16(sbase + SB_OFF(S) + (KKC) * 8192 + 4096 + my16,               \
                   Bb + bt + 4096 + my16);                                       \
    } while (0)

    // prologue: stage 0 fully
#pragma unroll
    for (int kk = 0; kk < K16_PER_STAGE; kk++) ISSUE_CHUNK(0, 0, kk);
    CP_COMMIT();

    int sread = 0;
#pragma unroll 1
    for (int st = 0; st < KSTAGES; st++) {
        CP_WAIT0();               // stage st resident (sole outstanding group)
        __syncthreads();

        const unsigned char* sA = smem + SA_OFF(sread);
        const unsigned char* sB = smem + SB_OFF(sread);
        const int swrite = sread ^ 1;
        const bool pf = (st + 1 < KSTAGES);

#pragma unroll
        for (int kk = 0; kk < K16_PER_STAGE; kk++) {
            // front-load next stage's 8 chunks into the first 4 compute chunks
            if (pf && kk < 4) {
                ISSUE_CHUNK(st + 1, swrite, 2 * kk);
                ISSUE_CHUNK(st + 1, swrite, 2 * kk + 1);
            }

            uint4 af[4];
            uint2 bf[8];
#pragma unroll
            for (int i = 0; i < 4; i++)
                af[i] = *(const uint4*)(sA + kk * 4096 + afro + i * 512);
#pragma unroll
            for (int j = 0; j < 8; j++)
                bf[j] = *(const uint2*)(sB + kk * 8192 + bfro + j * 256);
#pragma unroll
            for (int i = 0; i < 4; i++)
#pragma unroll
                for (int j = 0; j < 8; j++)
                    mma_bf16(acc[i][j], (const unsigned*)&af[i], (const unsigned*)&bf[j]);
        }
        CP_COMMIT();
        sread ^= 1;
    }

    // ---------------- epilogue: dequant + bias --------------------------------
    const int g = lid >> 2, tig = lid & 3;
#pragma unroll
    for (int i = 0; i < 4; i++) {
        int r0 = m0 + wm * 64 + i * 16 + g;
        int r1 = r0 + 8;
        float sa0 = g_sa[r0], sa1 = g_sa[r1];
#pragma unroll
        for (int j = 0; j < 8; j++) {
            int col = n0 + wn * 64 + j * 8 + tig * 2;
            float sw0 = g_sw[col], sw1 = g_sw[col + 1];
            float b0 = bias[col], b1 = bias[col + 1];
            float2 y0, y1;
            y0.x = acc[i][j][0] * (sa0 * sw0) + b0;
            y0.y = acc[i][j][1] * (sa0 * sw1) + b1;
            y1.x = acc[i][j][2] * (sa1 * sw0) + b0;
            y1.y = acc[i][j][3] * (sa1 * sw1) + b1;
            *(float2*)(out + (size_t)r0 * N_DIM + col) = y0;
            *(float2*)(out + (size_t)r1 * N_DIM + col) = y1;
        }
    }
}

// ---------------- launch -----------------------------------------------------
extern "C" void kernel_launch(void* const* d_in, const int* in_sizes, int n_in,
                              void* d_out, int out_size) {
    const float* x = (const float*)d_in[0];
    const float* w = (const float*)d_in[1];
    const float* bias = (const float*)d_in[2];
    float* out = (float*)d_out;

    cudaFuncSetAttribute(gemm_kernel, cudaFuncAttributeMaxDynamicSharedMemorySize,
                         SMEM_BYTES);

    quant_kernel<<<M_DIM + N_DIM, 256>>>(x, w);
    dim3 grid(N_DIM / BN, M_DIM / BM);
    gemm_kernel<<<grid, 256, SMEM_BYTES>>>(bias, out);
}